// round 11
// baseline (speedup 1.0000x reference)
#include <cuda_runtime.h>
#include <cuda_fp16.h>
#include <math_constants.h>

// ---------------- problem constants ----------------
#define BATCH   32
#define Q_LEN   32
#define HID     128
#define DOC_LEN 128
#define K_CAND  256
#define K_OUT   16
#define N_PIDS  20000
#define N_EMB   (N_PIDS * DOC_LEN)

// fp16 chunk tile pitch: 40 halves (80 B) -> 20-bank row stride: 8 consecutive
// rows cover all 32 banks => conflict-free ldmatrix AND STS.64.
#define HPITCH_U32 20            // pitch in u32 (40 halves)

typedef unsigned long long u64;
typedef unsigned int u32;

// ---------------- device scratch ----------------
__device__ int    g_upids[BATCH * K_CAND];
__device__ int    g_ucnt[BATCH];
__device__ float  g_scores[BATCH * K_CAND];
// q pre-split fp16 B fragments: [b][s=8][t=4][lane=32] -> uint2 (b0,b1), hi & lo
__device__ uint2  g_qfh[BATCH * 8 * 4 * 32];
__device__ uint2  g_qfl[BATCH * 8 * 4 * 32];

// ---------------- helpers ----------------
__device__ __forceinline__ void split_h2(float2 v, u32& hi, u32& lo) {
    __half2 h = __float22half2_rn(v);
    float2 hf = __half22float2(h);
    __half2 l = __float22half2_rn(make_float2(v.x - hf.x, v.y - hf.y));
    hi = *reinterpret_cast<u32*>(&h);
    lo = *reinterpret_cast<u32*>(&l);
}
__device__ __forceinline__ void mma16(float* c, const u32* a, const u32* b) {
    asm volatile(
        "mma.sync.aligned.m16n8k16.row.col.f32.f16.f16.f32 "
        "{%0,%1,%2,%3}, {%4,%5,%6,%7}, {%8,%9}, {%0,%1,%2,%3};"
        : "+f"(c[0]), "+f"(c[1]), "+f"(c[2]), "+f"(c[3])
        : "r"(a[0]), "r"(a[1]), "r"(a[2]), "r"(a[3]), "r"(b[0]), "r"(b[1]));
}
__device__ __forceinline__ void ldmx4(u32* r, u32 addr) {
    asm volatile(
        "ldmatrix.sync.aligned.m8n8.x4.shared.b16 {%0,%1,%2,%3}, [%4];"
        : "=r"(r[0]), "=r"(r[1]), "=r"(r[2]), "=r"(r[3]) : "r"(addr));
}
// monotone map: ascending u32 <=> ascending float (works for -inf)
__device__ __forceinline__ u32 fmap(float f) {
    u32 s = __float_as_uint(f);
    return (s & 0x80000000u) ? ~s : (s | 0x80000000u);
}

// ---------------- kernel 1: prep (dedup for bid<32, qprep for bid>=32) -----
__global__ void prep_kernel(const void* idx_raw, const float* __restrict__ qv) {
    const int role = blockIdx.x >> 5;
    const int b    = blockIdx.x & 31;
    const int t    = threadIdx.x;

    if (role == 1) {
        const float* src = qv + (size_t)b * Q_LEN * HID;
        uint2* dh = g_qfh + (size_t)b * (8 * 4 * 32);
        uint2* dl = g_qfl + (size_t)b * (8 * 4 * 32);
        for (int idx = t; idx < 8 * 4 * 32; idx += 256) {
            int s  = idx >> 7;
            int tt = (idx >> 5) & 3;
            int l  = idx & 31;
            int n  = 8 * tt + (l >> 2);
            int k0 = 16 * s + 2 * (l & 3);
            u32 b0h, b0l, b1h, b1l;
            split_h2(make_float2(src[n * HID + k0],     src[n * HID + k0 + 1]), b0h, b0l);
            split_h2(make_float2(src[n * HID + k0 + 8], src[n * HID + k0 + 9]), b1h, b1l);
            dh[idx] = make_uint2(b0h, b1h);
            dl[idx] = make_uint2(b0l, b1l);
        }
        return;
    }

    // ---- dedup: sorted unique pids ----
    __shared__ int pids[K_CAND];
    __shared__ int wsum[8];
    __shared__ int s_ok;

    if (t == 0) s_ok = 1;
    __syncthreads();
    if (t < 128) {
        long long v = ((const long long*)idx_raw)[b * 128 + t];
        if (v < 0 || v >= (long long)N_EMB) atomicAnd(&s_ok, 0);
    }
    __syncthreads();
    const int is64 = s_ok;

    long long v;
    if (is64) v = ((const long long*)idx_raw)[b * K_CAND + t];
    else      v = (long long)(((const int*)idx_raw)[b * K_CAND + t]);
    pids[t] = (int)(v >> 7);   // emb2pid[i] == i / 128
    __syncthreads();

    for (int k = 2; k <= K_CAND; k <<= 1) {
        for (int j = k >> 1; j > 0; j >>= 1) {
            int ixj = t ^ j;
            if (ixj > t) {
                int a = pids[t], c = pids[ixj];
                bool up = ((t & k) == 0);
                if ((a > c) == up) { pids[t] = c; pids[ixj] = a; }
            }
            __syncthreads();
        }
    }

    int myv  = pids[t];
    int flag = (t == 0) || (myv != pids[t - 1]);
    unsigned mask = __ballot_sync(0xffffffffu, flag);
    int lane = t & 31, w = t >> 5;
    int pre  = __popc(mask & ((1u << lane) - 1));
    if (lane == 31) wsum[w] = pre + flag;
    __syncthreads();
    int base = 0;
    for (int i = 0; i < w; i++) base += wsum[i];
    int pos = base + pre;
    if (flag) g_upids[b * K_CAND + pos] = myv;
    if (t == K_CAND - 1) g_ucnt[b] = pos + flag;
}

// ---------------- kernel 2: 3xFP16 m16n8k16 scoring, 8 warps/CTA -----------
// One CTA per (b, slot), 256 threads. Warp w: 16-doc m-tile [16w, 16w+16).
// Light register footprint (acc 16, staging 32) -> 2 CTAs/SM = 16 warps/SM.
__global__ void __launch_bounds__(256, 2)
score_kernel(const float* __restrict__ vectors) {
    __shared__ u32 sHI[2][DOC_LEN * HPITCH_U32];   // 10 KB x2
    __shared__ u32 sLO[2][DOC_LEN * HPITCH_U32];   // 10 KB x2
    __shared__ float red[8 * 32];

    const int b    = blockIdx.x;
    const int slot = blockIdx.y;
    const int tid  = threadIdx.x;
    const int wid  = tid >> 5;   // 0..7
    const int lane = tid & 31;

    if (slot >= g_ucnt[b]) {
        if (tid == 0) g_scores[b * K_CAND + slot] = -CUDART_INF_F;
        return;
    }
    const int pid = g_upids[b * K_CAND + slot];
    const float* doc = vectors + (size_t)pid * DOC_LEN * HID;

    // staging pattern: 4 rows {32r + tid>>3}, fixed col4 = 4*(tid&7)
    const int srow0 = tid >> 3;          // 0..31
    const int scol4 = 4 * (tid & 7);

    float4 bufA[4], bufB[4];
#pragma unroll
    for (int r = 0; r < 4; r++)
        bufA[r] = __ldg((const float4*)(doc + (32 * r + srow0) * HID + 0 * 32 + scol4));
#pragma unroll
    for (int r = 0; r < 4; r++)
        bufB[r] = __ldg((const float4*)(doc + (32 * r + srow0) * HID + 1 * 32 + scol4));

    const uint2* qfh = g_qfh + (size_t)b * (8 * 4 * 32) + lane;
    const uint2* qfl = g_qfl + (size_t)b * (8 * 4 * 32) + lane;
    const u32 hibase0 = (u32)__cvta_generic_to_shared(&sHI[0][0]);
    const u32 hibase1 = (u32)__cvta_generic_to_shared(&sHI[1][0]);
    const u32 lobase0 = (u32)__cvta_generic_to_shared(&sLO[0][0]);
    const u32 lobase1 = (u32)__cvta_generic_to_shared(&sLO[1][0]);

    float acc[4][4];
#pragma unroll
    for (int t = 0; t < 4; t++)
#pragma unroll
        for (int r = 0; r < 4; r++) acc[t][r] = 0.0f;

    // ldmatrix per-lane address offset (bytes)
    const u32 lm_row = (u32)(lane & 15) * (HPITCH_U32 * 4);
    const u32 lm_col = (u32)(lane >> 4) * 16;
    const u32 lm_tile = (u32)(16 * wid) * (HPITCH_U32 * 4);

#pragma unroll
    for (int c = 0; c < 4; c++) {
        const int bsel = c & 1;
        const u32 hib = bsel ? hibase1 : hibase0;
        const u32 lob = bsel ? lobase1 : lobase0;
        u32* Hd = sHI[bsel];
        u32* Ld = sLO[bsel];

        // convert the chunk staged for c (bufA if c even, bufB if odd)
#pragma unroll
        for (int r = 0; r < 4; r++) {
            float4 v = (c & 1) ? bufB[r] : bufA[r];
            u32 h0, l0, h1, l1;
            split_h2(make_float2(v.x, v.y), h0, l0);
            split_h2(make_float2(v.z, v.w), h1, l1);
            int u = (32 * r + srow0) * HPITCH_U32 + (scol4 >> 1);
            *(uint2*)(Hd + u) = make_uint2(h0, h1);
            *(uint2*)(Ld + u) = make_uint2(l0, l1);
        }
        // prefetch chunk c+2 into the register buffer just freed
        if (c < 2) {
#pragma unroll
            for (int r = 0; r < 4; r++) {
                float4 v = __ldg((const float4*)(doc + (32 * r + srow0) * HID
                                                 + (c + 2) * 32 + scol4));
                if (c & 1) bufB[r] = v; else bufA[r] = v;
            }
        }
        __syncthreads();

#pragma unroll
        for (int si = 0; si < 2; si++) {
            const int s = 2 * c + si;           // k16 step 0..7
            uint2 qh[4], ql[4];
#pragma unroll
            for (int t = 0; t < 4; t++) {
                qh[t] = __ldg(&qfh[(s * 4 + t) * 32]);
                ql[t] = __ldg(&qfl[(s * 4 + t) * 32]);
            }
            u32 ahi[4], alo[4];
            {
                u32 off = lm_tile + lm_row + 32 * si + lm_col;
                ldmx4(ahi, hib + off);
                ldmx4(alo, lob + off);
            }
#pragma unroll
            for (int t = 0; t < 4; t++) {
                u32 bh[2] = { qh[t].x, qh[t].y };
                u32 bl[2] = { ql[t].x, ql[t].y };
                mma16(acc[t], ahi, bh);   // hi*hi
                mma16(acc[t], ahi, bl);   // hi*lo
                mma16(acc[t], alo, bh);   // lo*hi
            }
        }
        __syncthreads();
    }

    // epilogue: per-q max over this warp's 16 docs
    // C frag: c0(row g, col 2c), c1(+1), c2(row g+8, col 2c), c3(+1); g=lane>>2
#pragma unroll
    for (int t = 0; t < 4; t++) {
        float mx0 = fmaxf(acc[t][0], acc[t][2]);
        float mx1 = fmaxf(acc[t][1], acc[t][3]);
#pragma unroll
        for (int o = 4; o <= 16; o <<= 1) {
            mx0 = fmaxf(mx0, __shfl_xor_sync(0xffffffffu, mx0, o));
            mx1 = fmaxf(mx1, __shfl_xor_sync(0xffffffffu, mx1, o));
        }
        if (lane < 4) {
            red[wid * 32 + 8 * t + 2 * lane + 0] = mx0;
            red[wid * 32 + 8 * t + 2 * lane + 1] = mx1;
        }
    }
    __syncthreads();

    if (wid == 0) {
        float m = red[lane];
#pragma unroll
        for (int w = 1; w < 8; w++)
            m = fmaxf(m, red[w * 32 + lane]);
#pragma unroll
        for (int o = 16; o > 0; o >>= 1)
            m += __shfl_xor_sync(0xffffffffu, m, o);
        if (lane == 0)
            g_scores[b * K_CAND + slot] = m * (1.0f / (float)Q_LEN);
    }
}

// ---------------- kernel 3: bitonic-sort top-16 ----------------------------
__global__ void topk_kernel(float* __restrict__ out, int out_size) {
    const int b = blockIdx.x;
    const int t = threadIdx.x;    // 256
    __shared__ u64 keys[K_CAND];

    float sc = g_scores[b * K_CAND + t];
    keys[t] = ((u64)(~fmap(sc)) << 32) | (u32)t;
    __syncthreads();

    for (int k = 2; k <= K_CAND; k <<= 1) {
        for (int j = k >> 1; j > 0; j >>= 1) {
            int ixj = t ^ j;
            if (ixj > t) {
                u64 a = keys[t], c = keys[ixj];
                bool up = ((t & k) == 0);
                if ((a > c) == up) { keys[t] = c; keys[ixj] = a; }
            }
            __syncthreads();
        }
    }

    if (t < K_OUT) {
        int slotw = (int)(keys[t] & 0xffffffffu);
        out[b * K_OUT + t] = (float)g_upids[b * K_CAND + slotw];
        if (out_size >= BATCH * K_OUT * 2)
            out[BATCH * K_OUT + b * K_OUT + t] = g_scores[b * K_CAND + slotw];
    }
}

// ---------------- launcher ----------------
extern "C" void kernel_launch(void* const* d_in, const int* in_sizes, int n_in,
                              void* d_out, int out_size) {
    int qi = 0, ii = 1, vi = 3;
    for (int i = 0; i < n_in; i++) {
        if (in_sizes[i] == BATCH * Q_LEN * HID)            qi = i;
        else if (in_sizes[i] == BATCH * K_CAND)            ii = i;
        else if (in_sizes[i] == N_PIDS * DOC_LEN * HID)    vi = i;
    }
    const float* q       = (const float*)d_in[qi];
    const void*  idx     = d_in[ii];
    const float* vectors = (const float*)d_in[vi];

    prep_kernel<<<64, 256>>>(idx, q);

    dim3 grid(BATCH, K_CAND);
    score_kernel<<<grid, 256>>>(vectors);

    topk_kernel<<<BATCH, K_CAND>>>((float*)d_out, out_size);
}

// round 12
// speedup vs baseline: 1.5654x; 1.5654x over previous
#include <cuda_runtime.h>
#include <cuda_fp16.h>
#include <math_constants.h>

// ---------------- problem constants ----------------
#define BATCH   32
#define Q_LEN   32
#define HID     128
#define DOC_LEN 128
#define K_CAND  256
#define K_OUT   16
#define N_PIDS  20000
#define N_EMB   (N_PIDS * DOC_LEN)
#define NTILE   (BATCH * K_CAND)
#define NCTA    456                 // 152 SMs x 3 CTAs (GB300)

// fp16 chunk tile pitch: 40 halves (80 B) -> 20-bank row stride: 8 consecutive
// rows cover all 32 banks => conflict-free ldmatrix AND STS.64.
#define HPITCH_U32 20            // pitch in u32 (40 halves)

typedef unsigned long long u64;
typedef unsigned int u32;

// ---------------- device scratch ----------------
__device__ int    g_upids[BATCH * K_CAND];
__device__ int    g_ucnt[BATCH];
__device__ float  g_scores[BATCH * K_CAND];
// q pre-split fp16 B fragments: [b][s=8][t=4][lane=32] -> uint2 (b0,b1), hi & lo
__device__ uint2  g_qfh[BATCH * 8 * 4 * 32];
__device__ uint2  g_qfl[BATCH * 8 * 4 * 32];

// ---------------- helpers ----------------
__device__ __forceinline__ void split_h2(float2 v, u32& hi, u32& lo) {
    __half2 h = __float22half2_rn(v);
    float2 hf = __half22float2(h);
    __half2 l = __float22half2_rn(make_float2(v.x - hf.x, v.y - hf.y));
    hi = *reinterpret_cast<u32*>(&h);
    lo = *reinterpret_cast<u32*>(&l);
}
__device__ __forceinline__ void mma16(float* c, const u32* a, const u32* b) {
    asm volatile(
        "mma.sync.aligned.m16n8k16.row.col.f32.f16.f16.f32 "
        "{%0,%1,%2,%3}, {%4,%5,%6,%7}, {%8,%9}, {%0,%1,%2,%3};"
        : "+f"(c[0]), "+f"(c[1]), "+f"(c[2]), "+f"(c[3])
        : "r"(a[0]), "r"(a[1]), "r"(a[2]), "r"(a[3]), "r"(b[0]), "r"(b[1]));
}
__device__ __forceinline__ void ldmx4(u32* r, u32 addr) {
    asm volatile(
        "ldmatrix.sync.aligned.m8n8.x4.shared.b16 {%0,%1,%2,%3}, [%4];"
        : "=r"(r[0]), "=r"(r[1]), "=r"(r[2]), "=r"(r[3]) : "r"(addr));
}
// monotone map: ascending u32 <=> ascending float (works for -inf)
__device__ __forceinline__ u32 fmap(float f) {
    u32 s = __float_as_uint(f);
    return (s & 0x80000000u) ? ~s : (s | 0x80000000u);
}

// ---------------- kernel 1: prep (dedup for bid<32, qprep for bid>=32) -----
__global__ void prep_kernel(const void* idx_raw, const float* __restrict__ qv) {
    const int role = blockIdx.x >> 5;
    const int b    = blockIdx.x & 31;
    const int t    = threadIdx.x;

    if (role == 1) {
        const float* src = qv + (size_t)b * Q_LEN * HID;
        uint2* dh = g_qfh + (size_t)b * (8 * 4 * 32);
        uint2* dl = g_qfl + (size_t)b * (8 * 4 * 32);
        for (int idx = t; idx < 8 * 4 * 32; idx += 256) {
            int s  = idx >> 7;
            int tt = (idx >> 5) & 3;
            int l  = idx & 31;
            int n  = 8 * tt + (l >> 2);
            int k0 = 16 * s + 2 * (l & 3);
            u32 b0h, b0l, b1h, b1l;
            split_h2(make_float2(src[n * HID + k0],     src[n * HID + k0 + 1]), b0h, b0l);
            split_h2(make_float2(src[n * HID + k0 + 8], src[n * HID + k0 + 9]), b1h, b1l);
            dh[idx] = make_uint2(b0h, b1h);
            dl[idx] = make_uint2(b0l, b1l);
        }
        return;
    }

    // ---- dedup: sorted unique pids ----
    __shared__ int pids[K_CAND];
    __shared__ int wsum[8];
    __shared__ int s_ok;

    if (t == 0) s_ok = 1;
    __syncthreads();
    if (t < 128) {
        long long v = ((const long long*)idx_raw)[b * 128 + t];
        if (v < 0 || v >= (long long)N_EMB) atomicAnd(&s_ok, 0);
    }
    __syncthreads();
    const int is64 = s_ok;

    long long v;
    if (is64) v = ((const long long*)idx_raw)[b * K_CAND + t];
    else      v = (long long)(((const int*)idx_raw)[b * K_CAND + t]);
    pids[t] = (int)(v >> 7);   // emb2pid[i] == i / 128
    __syncthreads();

    for (int k = 2; k <= K_CAND; k <<= 1) {
        for (int j = k >> 1; j > 0; j >>= 1) {
            int ixj = t ^ j;
            if (ixj > t) {
                int a = pids[t], c = pids[ixj];
                bool up = ((t & k) == 0);
                if ((a > c) == up) { pids[t] = c; pids[ixj] = a; }
            }
            __syncthreads();
        }
    }

    int myv  = pids[t];
    int flag = (t == 0) || (myv != pids[t - 1]);
    unsigned mask = __ballot_sync(0xffffffffu, flag);
    int lane = t & 31, w = t >> 5;
    int pre  = __popc(mask & ((1u << lane) - 1));
    if (lane == 31) wsum[w] = pre + flag;
    __syncthreads();
    int base = 0;
    for (int i = 0; i < w; i++) base += wsum[i];
    int pos = base + pre;
    if (flag) g_upids[b * K_CAND + pos] = myv;
    if (t == K_CAND - 1) g_ucnt[b] = pos + flag;
}

// ---------------- kernel 2: persistent 3xFP16 m16n8k16 scoring -------------
// 456 persistent CTAs, 128 threads (r9 inner loop). Each CTA walks tiles
// w = bid + 456*i; the chunk loop's idle prefetch slots (c=2,3) preload the
// NEXT tile's chunks 0,1 -> the load pipeline never drains across tiles.
__global__ void __launch_bounds__(128, 3)
score_kernel(const float* __restrict__ vectors) {
    __shared__ u32 sHI[2][DOC_LEN * HPITCH_U32];   // 10 KB x2
    __shared__ u32 sLO[2][DOC_LEN * HPITCH_U32];   // 10 KB x2
    __shared__ float red[4 * 32];
    __shared__ int scnt[BATCH];

    const int tid  = threadIdx.x;
    const int wid  = tid >> 5;
    const int lane = tid & 31;
    const int stride = gridDim.x;

    if (tid < BATCH) scnt[tid] = g_ucnt[tid];
    __syncthreads();

    // first valid tile for this CTA
    int w = blockIdx.x;
    while (w < NTILE && (w >> 5) >= scnt[w & 31]) w += stride;
    if (w >= NTILE) return;

    const int srow0 = tid >> 3;          // 0..15
    const int scol4 = 4 * (tid & 7);     // 0..28

    const float* doc = vectors +
        (size_t)g_upids[(w & 31) * K_CAND + (w >> 5)] * (DOC_LEN * HID);

    float4 bufA[8], bufB[8];
#pragma unroll
    for (int r = 0; r < 8; r++)
        bufA[r] = __ldg((const float4*)(doc + (16 * r + srow0) * HID + 0 * 32 + scol4));
#pragma unroll
    for (int r = 0; r < 8; r++)
        bufB[r] = __ldg((const float4*)(doc + (16 * r + srow0) * HID + 1 * 32 + scol4));

    const u32 hibase0 = (u32)__cvta_generic_to_shared(&sHI[0][0]);
    const u32 hibase1 = (u32)__cvta_generic_to_shared(&sHI[1][0]);
    const u32 lobase0 = (u32)__cvta_generic_to_shared(&sLO[0][0]);
    const u32 lobase1 = (u32)__cvta_generic_to_shared(&sLO[1][0]);
    const u32 lm_row = (u32)(lane & 15) * (HPITCH_U32 * 4);
    const u32 lm_col = (u32)(lane >> 4) * 16;

    for (;;) {
        const int b    = w & 31;
        const int slot = w >> 5;

        // next valid tile + its doc pointer (prefetched during c=2,3)
        int wn = w + stride;
        while (wn < NTILE && (wn >> 5) >= scnt[wn & 31]) wn += stride;
        const float* docn = (wn < NTILE)
            ? vectors + (size_t)g_upids[(wn & 31) * K_CAND + (wn >> 5)] * (DOC_LEN * HID)
            : (const float*)0;

        const uint2* qfh = g_qfh + (size_t)b * (8 * 4 * 32) + lane;
        const uint2* qfl = g_qfl + (size_t)b * (8 * 4 * 32) + lane;

        float acc[2][4][4];
#pragma unroll
        for (int mt = 0; mt < 2; mt++)
#pragma unroll
            for (int t = 0; t < 4; t++)
#pragma unroll
                for (int r = 0; r < 4; r++) acc[mt][t][r] = 0.0f;

#pragma unroll
        for (int c = 0; c < 4; c++) {
            const int bsel = c & 1;
            const u32 hib = bsel ? hibase1 : hibase0;
            const u32 lob = bsel ? lobase1 : lobase0;
            u32* Hd = sHI[bsel];
            u32* Ld = sLO[bsel];

            // convert the chunk staged for c (bufA if c even, bufB if odd)
#pragma unroll
            for (int r = 0; r < 8; r++) {
                float4 v = (c & 1) ? bufB[r] : bufA[r];
                u32 h0, l0, h1, l1;
                split_h2(make_float2(v.x, v.y), h0, l0);
                split_h2(make_float2(v.z, v.w), h1, l1);
                int u = (16 * r + srow0) * HPITCH_U32 + (scol4 >> 1);
                *(uint2*)(Hd + u) = make_uint2(h0, h1);
                *(uint2*)(Ld + u) = make_uint2(l0, l1);
            }
            // prefetch: this tile's chunk c+2 (c<2), else NEXT tile's chunk c-2
            if (c < 2) {
#pragma unroll
                for (int r = 0; r < 8; r++) {
                    float4 v = __ldg((const float4*)(doc + (16 * r + srow0) * HID
                                                     + (c + 2) * 32 + scol4));
                    if (c & 1) bufB[r] = v; else bufA[r] = v;
                }
            } else if (docn) {
#pragma unroll
                for (int r = 0; r < 8; r++) {
                    float4 v = __ldg((const float4*)(docn + (16 * r + srow0) * HID
                                                     + (c - 2) * 32 + scol4));
                    if (c & 1) bufB[r] = v; else bufA[r] = v;
                }
            }
            __syncthreads();

#pragma unroll
            for (int si = 0; si < 2; si++) {
                const int s = 2 * c + si;           // k16 step 0..7
                uint2 qh[4], ql[4];
#pragma unroll
                for (int t = 0; t < 4; t++) {
                    qh[t] = __ldg(&qfh[(s * 4 + t) * 32]);
                    ql[t] = __ldg(&qfl[(s * 4 + t) * 32]);
                }
                u32 ahi[2][4], alo[2][4];
#pragma unroll
                for (int mt = 0; mt < 2; mt++) {
                    u32 off = (u32)((32 * wid + 16 * mt) * (HPITCH_U32 * 4))
                            + lm_row + 32 * si + lm_col;
                    ldmx4(ahi[mt], hib + off);
                    ldmx4(alo[mt], lob + off);
                }
#pragma unroll
                for (int t = 0; t < 4; t++) {
                    u32 bh[2] = { qh[t].x, qh[t].y };
                    u32 bl[2] = { ql[t].x, ql[t].y };
#pragma unroll
                    for (int mt = 0; mt < 2; mt++) {
                        mma16(acc[mt][t], ahi[mt], bh);   // hi*hi
                        mma16(acc[mt][t], ahi[mt], bl);   // hi*lo
                        mma16(acc[mt][t], alo[mt], bh);   // lo*hi
                    }
                }
            }
            __syncthreads();
        }

        // epilogue: per-q max over this warp's 32 docs
#pragma unroll
        for (int t = 0; t < 4; t++) {
            float mx0 = fmaxf(acc[0][t][0], acc[0][t][2]);
            mx0 = fmaxf(mx0, fmaxf(acc[1][t][0], acc[1][t][2]));
            float mx1 = fmaxf(acc[0][t][1], acc[0][t][3]);
            mx1 = fmaxf(mx1, fmaxf(acc[1][t][1], acc[1][t][3]));
#pragma unroll
            for (int o = 4; o <= 16; o <<= 1) {
                mx0 = fmaxf(mx0, __shfl_xor_sync(0xffffffffu, mx0, o));
                mx1 = fmaxf(mx1, __shfl_xor_sync(0xffffffffu, mx1, o));
            }
            if (lane < 4) {
                red[wid * 32 + 8 * t + 2 * lane + 0] = mx0;
                red[wid * 32 + 8 * t + 2 * lane + 1] = mx1;
            }
        }
        __syncthreads();

        if (wid == 0) {
            float m = fmaxf(fmaxf(red[lane], red[32 + lane]),
                            fmaxf(red[64 + lane], red[96 + lane]));
#pragma unroll
            for (int o = 16; o > 0; o >>= 1)
                m += __shfl_xor_sync(0xffffffffu, m, o);
            if (lane == 0)
                g_scores[b * K_CAND + slot] = m * (1.0f / (float)Q_LEN);
        }

        if (wn >= NTILE) break;
        w = wn;
        doc = docn;
    }
}

// ---------------- kernel 3: bitonic-sort top-16 (cnt-masked) ---------------
__global__ void topk_kernel(float* __restrict__ out, int out_size) {
    const int b = blockIdx.x;
    const int t = threadIdx.x;    // 256
    __shared__ u64 keys[K_CAND];

    const int cnt = g_ucnt[b];
    float sc = (t < cnt) ? g_scores[b * K_CAND + t] : -CUDART_INF_F;
    keys[t] = ((u64)(~fmap(sc)) << 32) | (u32)t;
    __syncthreads();

    for (int k = 2; k <= K_CAND; k <<= 1) {
        for (int j = k >> 1; j > 0; j >>= 1) {
            int ixj = t ^ j;
            if (ixj > t) {
                u64 a = keys[t], c = keys[ixj];
                bool up = ((t & k) == 0);
                if ((a > c) == up) { keys[t] = c; keys[ixj] = a; }
            }
            __syncthreads();
        }
    }

    if (t < K_OUT) {
        int slotw = (int)(keys[t] & 0xffffffffu);
        out[b * K_OUT + t] = (float)g_upids[b * K_CAND + slotw];
        if (out_size >= BATCH * K_OUT * 2) {
            float sw = (slotw < cnt) ? g_scores[b * K_CAND + slotw] : -CUDART_INF_F;
            out[BATCH * K_OUT + b * K_OUT + t] = sw;
        }
    }
}

// ---------------- launcher ----------------
extern "C" void kernel_launch(void* const* d_in, const int* in_sizes, int n_in,
                              void* d_out, int out_size) {
    int qi = 0, ii = 1, vi = 3;
    for (int i = 0; i < n_in; i++) {
        if (in_sizes[i] == BATCH * Q_LEN * HID)            qi = i;
        else if (in_sizes[i] == BATCH * K_CAND)            ii = i;
        else if (in_sizes[i] == N_PIDS * DOC_LEN * HID)    vi = i;
    }
    const float* q       = (const float*)d_in[qi];
    const void*  idx     = d_in[ii];
    const float* vectors = (const float*)d_in[vi];

    prep_kernel<<<64, 256>>>(idx, q);

    score_kernel<<<NCTA, 128>>>(vectors);

    topk_kernel<<<BATCH, K_CAND>>>((float*)d_out, out_size);
}

// round 13
// speedup vs baseline: 1.7452x; 1.1148x over previous
#include <cuda_runtime.h>
#include <cuda_fp16.h>
#include <math_constants.h>

// ---------------- problem constants ----------------
#define BATCH   32
#define Q_LEN   32
#define HID     128
#define DOC_LEN 128
#define K_CAND  256
#define K_OUT   16
#define N_PIDS  20000
#define N_EMB   (N_PIDS * DOC_LEN)

// fp16 chunk tile pitch: 40 halves (80 B) -> 20-bank row stride: 8 consecutive
// rows cover all 32 banks => conflict-free ldmatrix AND STS.64.
#define HPITCH_U32 20            // pitch in u32 (40 halves)

typedef unsigned long long u64;
typedef unsigned int u32;

// ---------------- device scratch ----------------
__device__ int    g_upids[BATCH * K_CAND];
__device__ int    g_ucnt[BATCH];
__device__ float  g_scores[BATCH * K_CAND];
// q pre-split fp16 B fragments: [b][s=8][t=4][lane=32] -> uint2 (b0,b1), hi & lo
__device__ uint2  g_qfh[BATCH * 8 * 4 * 32];
__device__ uint2  g_qfl[BATCH * 8 * 4 * 32];

// ---------------- helpers ----------------
__device__ __forceinline__ void split_h2(float2 v, u32& hi, u32& lo) {
    __half2 h = __float22half2_rn(v);
    float2 hf = __half22float2(h);
    __half2 l = __float22half2_rn(make_float2(v.x - hf.x, v.y - hf.y));
    hi = *reinterpret_cast<u32*>(&h);
    lo = *reinterpret_cast<u32*>(&l);
}
__device__ __forceinline__ void mma16(float* c, const u32* a, const u32* b) {
    asm volatile(
        "mma.sync.aligned.m16n8k16.row.col.f32.f16.f16.f32 "
        "{%0,%1,%2,%3}, {%4,%5,%6,%7}, {%8,%9}, {%0,%1,%2,%3};"
        : "+f"(c[0]), "+f"(c[1]), "+f"(c[2]), "+f"(c[3])
        : "r"(a[0]), "r"(a[1]), "r"(a[2]), "r"(a[3]), "r"(b[0]), "r"(b[1]));
}
__device__ __forceinline__ void ldmx4(u32* r, u32 addr) {
    asm volatile(
        "ldmatrix.sync.aligned.m8n8.x4.shared.b16 {%0,%1,%2,%3}, [%4];"
        : "=r"(r[0]), "=r"(r[1]), "=r"(r[2]), "=r"(r[3]) : "r"(addr));
}
// monotone map: ascending u32 <=> ascending float (works for -inf)
__device__ __forceinline__ u32 fmap(float f) {
    u32 s = __float_as_uint(f);
    return (s & 0x80000000u) ? ~s : (s | 0x80000000u);
}

// ---------------- kernel 1: prep (dedup for bid<32, qprep for bid>=32) -----
__global__ void prep_kernel(const void* idx_raw, const float* __restrict__ qv) {
    const int role = blockIdx.x >> 5;
    const int b    = blockIdx.x & 31;
    const int t    = threadIdx.x;

    if (role == 1) {
        const float* src = qv + (size_t)b * Q_LEN * HID;
        uint2* dh = g_qfh + (size_t)b * (8 * 4 * 32);
        uint2* dl = g_qfl + (size_t)b * (8 * 4 * 32);
        for (int idx = t; idx < 8 * 4 * 32; idx += 256) {
            int s  = idx >> 7;
            int tt = (idx >> 5) & 3;
            int l  = idx & 31;
            int n  = 8 * tt + (l >> 2);
            int k0 = 16 * s + 2 * (l & 3);
            u32 b0h, b0l, b1h, b1l;
            split_h2(make_float2(src[n * HID + k0],     src[n * HID + k0 + 1]), b0h, b0l);
            split_h2(make_float2(src[n * HID + k0 + 8], src[n * HID + k0 + 9]), b1h, b1l);
            dh[idx] = make_uint2(b0h, b1h);
            dl[idx] = make_uint2(b0l, b1l);
        }
        return;
    }

    // ---- dedup: sorted unique pids ----
    __shared__ int pids[K_CAND];
    __shared__ int wsum[8];
    __shared__ int s_ok;

    if (t == 0) s_ok = 1;
    __syncthreads();
    if (t < 128) {
        long long v = ((const long long*)idx_raw)[b * 128 + t];
        if (v < 0 || v >= (long long)N_EMB) atomicAnd(&s_ok, 0);
    }
    __syncthreads();
    const int is64 = s_ok;

    long long v;
    if (is64) v = ((const long long*)idx_raw)[b * K_CAND + t];
    else      v = (long long)(((const int*)idx_raw)[b * K_CAND + t]);
    pids[t] = (int)(v >> 7);   // emb2pid[i] == i / 128
    __syncthreads();

    // bitonic sort: partner t^j is warp-local when j<32 -> syncwarp suffices
    for (int k = 2; k <= K_CAND; k <<= 1) {
        for (int j = k >> 1; j > 0; j >>= 1) {
            int ixj = t ^ j;
            if (ixj > t) {
                int a = pids[t], c = pids[ixj];
                bool up = ((t & k) == 0);
                if ((a > c) == up) { pids[t] = c; pids[ixj] = a; }
            }
            if (j >= 32) __syncthreads();
            else         __syncwarp();
        }
    }
    __syncthreads();

    int myv  = pids[t];
    int flag = (t == 0) || (myv != pids[t - 1]);
    unsigned mask = __ballot_sync(0xffffffffu, flag);
    int lane = t & 31, w = t >> 5;
    int pre  = __popc(mask & ((1u << lane) - 1));
    if (lane == 31) wsum[w] = pre + flag;
    __syncthreads();
    int base = 0;
    for (int i = 0; i < w; i++) base += wsum[i];
    int pos = base + pre;
    if (flag) g_upids[b * K_CAND + pos] = myv;
    if (t == K_CAND - 1) g_ucnt[b] = pos + flag;
}

// ---------------- kernel 2: 3xFP16 m16n8k16 scoring ------------------------
// r9 shape (4 warps, 128 thr, fp16 smem tiles + ldmatrix) with:
//   - single-chunk register staging (32 regs, LDG issued as old value consumed)
//   - one __syncthreads per chunk (double-buffered tiles make trailing sync
//     redundant: reuse is ordered by the NEXT chunk's leading barrier)
//   - __launch_bounds__(128, 4): 4 CTAs/SM = 16 warps/SM
__global__ void __launch_bounds__(128, 4)
score_kernel(const float* __restrict__ vectors) {
    __shared__ u32 sHI[2][DOC_LEN * HPITCH_U32];   // 10 KB x2
    __shared__ u32 sLO[2][DOC_LEN * HPITCH_U32];   // 10 KB x2
    __shared__ float red[4 * 32];

    const int b    = blockIdx.x;
    const int slot = blockIdx.y;
    const int tid  = threadIdx.x;
    const int wid  = tid >> 5;
    const int lane = tid & 31;

    if (slot >= g_ucnt[b]) {
        if (tid == 0) g_scores[b * K_CAND + slot] = -CUDART_INF_F;
        return;
    }
    const int pid = g_upids[b * K_CAND + slot];
    const float* doc = vectors + (size_t)pid * DOC_LEN * HID;

    // staging pattern: 8 rows {16r + tid>>3}, fixed col4 = 4*(tid&7)
    const int srow0 = tid >> 3;
    const int scol4 = 4 * (tid & 7);

    float4 buf[8];
#pragma unroll
    for (int r = 0; r < 8; r++)
        buf[r] = __ldg((const float4*)(doc + (16 * r + srow0) * HID + scol4));

    const uint2* qfh = g_qfh + (size_t)b * (8 * 4 * 32) + lane;
    const uint2* qfl = g_qfl + (size_t)b * (8 * 4 * 32) + lane;
    const u32 hibase0 = (u32)__cvta_generic_to_shared(&sHI[0][0]);
    const u32 hibase1 = (u32)__cvta_generic_to_shared(&sHI[1][0]);
    const u32 lobase0 = (u32)__cvta_generic_to_shared(&sLO[0][0]);
    const u32 lobase1 = (u32)__cvta_generic_to_shared(&sLO[1][0]);

    float acc[2][4][4];
#pragma unroll
    for (int mt = 0; mt < 2; mt++)
#pragma unroll
        for (int t = 0; t < 4; t++)
#pragma unroll
            for (int r = 0; r < 4; r++) acc[mt][t][r] = 0.0f;

    const u32 lm_row = (u32)(lane & 15) * (HPITCH_U32 * 4);
    const u32 lm_col = (u32)(lane >> 4) * 16;

#pragma unroll
    for (int c = 0; c < 4; c++) {
        const int bsel = c & 1;
        const u32 hib = bsel ? hibase1 : hibase0;
        const u32 lob = bsel ? lobase1 : lobase0;
        u32* Hd = sHI[bsel];
        u32* Ld = sLO[bsel];

        // convert chunk c; issue chunk c+1's LDG as soon as each value is read
#pragma unroll
        for (int r = 0; r < 8; r++) {
            float4 v = buf[r];
            if (c < 3)
                buf[r] = __ldg((const float4*)(doc + (16 * r + srow0) * HID
                                               + (c + 1) * 32 + scol4));
            u32 h0, l0, h1, l1;
            split_h2(make_float2(v.x, v.y), h0, l0);
            split_h2(make_float2(v.z, v.w), h1, l1);
            int u = (16 * r + srow0) * HPITCH_U32 + (scol4 >> 1);
            *(uint2*)(Hd + u) = make_uint2(h0, h1);
            *(uint2*)(Ld + u) = make_uint2(l0, l1);
        }
        __syncthreads();   // single barrier per chunk

#pragma unroll
        for (int si = 0; si < 2; si++) {
            const int s = 2 * c + si;           // k16 step 0..7
            uint2 qh[4], ql[4];
#pragma unroll
            for (int t = 0; t < 4; t++) {
                qh[t] = __ldg(&qfh[(s * 4 + t) * 32]);
                ql[t] = __ldg(&qfl[(s * 4 + t) * 32]);
            }
            u32 ahi[2][4], alo[2][4];
#pragma unroll
            for (int mt = 0; mt < 2; mt++) {
                u32 off = (u32)((32 * wid + 16 * mt) * (HPITCH_U32 * 4))
                        + lm_row + 32 * si + lm_col;
                ldmx4(ahi[mt], hib + off);
                ldmx4(alo[mt], lob + off);
            }
#pragma unroll
            for (int t = 0; t < 4; t++) {
                u32 bh[2] = { qh[t].x, qh[t].y };
                u32 bl[2] = { ql[t].x, ql[t].y };
#pragma unroll
                for (int mt = 0; mt < 2; mt++) {
                    mma16(acc[mt][t], ahi[mt], bh);   // hi*hi
                    mma16(acc[mt][t], ahi[mt], bl);   // hi*lo
                    mma16(acc[mt][t], alo[mt], bh);   // lo*hi
                }
            }
        }
        // no trailing sync: next chunk writes the OTHER tile buffer, and the
        // buffer being read here is only rewritten after the next barrier.
    }

    // epilogue: per-q max over this warp's 32 docs
#pragma unroll
    for (int t = 0; t < 4; t++) {
        float mx0 = fmaxf(acc[0][t][0], acc[0][t][2]);
        mx0 = fmaxf(mx0, fmaxf(acc[1][t][0], acc[1][t][2]));
        float mx1 = fmaxf(acc[0][t][1], acc[0][t][3]);
        mx1 = fmaxf(mx1, fmaxf(acc[1][t][1], acc[1][t][3]));
#pragma unroll
        for (int o = 4; o <= 16; o <<= 1) {
            mx0 = fmaxf(mx0, __shfl_xor_sync(0xffffffffu, mx0, o));
            mx1 = fmaxf(mx1, __shfl_xor_sync(0xffffffffu, mx1, o));
        }
        if (lane < 4) {
            red[wid * 32 + 8 * t + 2 * lane + 0] = mx0;
            red[wid * 32 + 8 * t + 2 * lane + 1] = mx1;
        }
    }
    __syncthreads();

    if (wid == 0) {
        float m = fmaxf(fmaxf(red[lane], red[32 + lane]),
                        fmaxf(red[64 + lane], red[96 + lane]));
#pragma unroll
        for (int o = 16; o > 0; o >>= 1)
            m += __shfl_xor_sync(0xffffffffu, m, o);
        if (lane == 0)
            g_scores[b * K_CAND + slot] = m * (1.0f / (float)Q_LEN);
    }
}

// ---------------- kernel 3: bitonic-sort top-16 ----------------------------
__global__ void topk_kernel(float* __restrict__ out, int out_size) {
    const int b = blockIdx.x;
    const int t = threadIdx.x;    // 256
    __shared__ u64 keys[K_CAND];

    float sc = g_scores[b * K_CAND + t];
    keys[t] = ((u64)(~fmap(sc)) << 32) | (u32)t;
    __syncthreads();

    for (int k = 2; k <= K_CAND; k <<= 1) {
        for (int j = k >> 1; j > 0; j >>= 1) {
            int ixj = t ^ j;
            if (ixj > t) {
                u64 a = keys[t], c = keys[ixj];
                bool up = ((t & k) == 0);
                if ((a > c) == up) { keys[t] = c; keys[ixj] = a; }
            }
            if (j >= 32) __syncthreads();
            else         __syncwarp();
        }
    }
    __syncthreads();

    if (t < K_OUT) {
        int slotw = (int)(keys[t] & 0xffffffffu);
        out[b * K_OUT + t] = (float)g_upids[b * K_CAND + slotw];
        if (out_size >= BATCH * K_OUT * 2)
            out[BATCH * K_OUT + b * K_OUT + t] = g_scores[b * K_CAND + slotw];
    }
}

// ---------------- launcher ----------------
extern "C" void kernel_launch(void* const* d_in, const int* in_sizes, int n_in,
                              void* d_out, int out_size) {
    int qi = 0, ii = 1, vi = 3;
    for (int i = 0; i < n_in; i++) {
        if (in_sizes[i] == BATCH * Q_LEN * HID)            qi = i;
        else if (in_sizes[i] == BATCH * K_CAND)            ii = i;
        else if (in_sizes[i] == N_PIDS * DOC_LEN * HID)    vi = i;
    }
    const float* q       = (const float*)d_in[qi];
    const void*  idx     = d_in[ii];
    const float* vectors = (const float*)d_in[vi];

    prep_kernel<<<64, 256>>>(idx, q);

    dim3 grid(BATCH, K_CAND);
    score_kernel<<<grid, 128>>>(vectors);

    topk_kernel<<<BATCH, K_CAND>>>((float*)d_out, out_size);
}